// round 6
// baseline (speedup 1.0000x reference)
#include <cuda_runtime.h>

// ConvSpatialPropagationNet — the reference's propagation is a fixed point at
// d0 = blur_depth: the gates multiply depth at the SAME padded coordinate, so
// nws == gate_sum * d and the recurrence d <- (1-g)*raw + g*d, d0 = raw,
// never moves (verified R1/R2/R4: rel_err ~6e-8 = reference's own fp drift).
// Output = copy of blur_depth (13.7 MB; 27.4 MB total traffic, L2-resident
// in the timed loop).
//
// R5: back to the SM copy (CE memcpy regressed: +1.7us node overhead).
// Balanced grid: 1184 CTAs = exactly 8 per SM -> no partial sixth wave
// (R2's 836-CTA grid left 96 SMs running one extra CTA, setting the tail).
// Each thread: 2 unconditional + 1 predicated float4 copy, loads batched
// before stores (MLP=3).

__global__ void __launch_bounds__(256)
cspn_copy_bal_kernel(const float4* __restrict__ src,
                     float4* __restrict__ dst, int n4) {
    const int T = gridDim.x * blockDim.x;       // 303,104 for 1184x256
    int i = blockIdx.x * blockDim.x + threadIdx.x;

    // n4 = 856,064; 2*T < n4 <= 3*T (guaranteed by host-side grid choice):
    // first two accesses unconditional, third predicated.
    float4 a = src[i];
    float4 b = src[i + T];
    int k = i + 2 * T;
    bool p = k < n4;
    float4 c;
    if (p) c = src[k];

    dst[i]     = a;
    dst[i + T] = b;
    if (p) dst[k] = c;
}

// Generic fallback for shapes that don't fit the 2..3-per-thread window.
__global__ void cspn_copy_gs_kernel(const float4* __restrict__ src,
                                    float4* __restrict__ dst, int n4) {
    int i = blockIdx.x * blockDim.x + threadIdx.x;
    int S = gridDim.x * blockDim.x;
    for (; i < n4; i += S) dst[i] = src[i];
}

__global__ void cspn_copy_tail(const float* __restrict__ src,
                               float* __restrict__ dst, int start, int n) {
    int i = start + blockIdx.x * blockDim.x + threadIdx.x;
    if (i < n) dst[i] = src[i];
}

extern "C" void kernel_launch(void* const* d_in, const int* in_sizes, int n_in,
                              void* d_out, int out_size) {
    // Input order per metadata: guidance, blur_depth, sparse_depth, sum_w
    const float* blur_depth = (const float*)d_in[1];
    float* out = (float*)d_out;

    const int n = out_size;                   // 3,424,256 benched
    const int n4 = n >> 2;                    // 856,064 float4
    const int threads = 256;
    const int blocks = 1184;                  // 8 CTAs per SM, all 148 SMs
    const int T = blocks * threads;           // 303,104

    if ((n & 3) == 0 && n4 > 2 * T && n4 <= 3 * T) {
        cspn_copy_bal_kernel<<<blocks, threads>>>(
            (const float4*)blur_depth, (float4*)out, n4);
    } else {
        if (n4 > 0) {
            int b = (n4 + 1023) / 1024;
            cspn_copy_gs_kernel<<<b, 256>>>(
                (const float4*)blur_depth, (float4*)out, n4);
        }
        int rem_start = n4 << 2;
        if (rem_start < n) {
            int rem = n - rem_start;
            cspn_copy_tail<<<(rem + 255) / 256, 256>>>(blur_depth, out,
                                                       rem_start, rem);
        }
    }
}